// round 16
// baseline (speedup 1.0000x reference)
#include <cuda_runtime.h>
#include <cuda_fp16.h>

#define NN 50000
#define EMB 35
#define DEG 32
#define HPAD 64      // fp16 row pad: 64 halves = 128 B (one L1 line, aligned)
#define APAD 36      // fp32 padded row: 36 floats = 144 B (16B aligned for float4)

typedef unsigned long long ull;

// ---- prep buffer layout (floats) ----
#define WCSZ  (36*72)                 // Wc per tag, padded to 36 rows x 72 cols
#define WCOFF 0                       // 4 tags
#define VOFF  (4*WCSZ)                // v vectors, 4*35
#define COFF  (VOFF + 4*EMB)          // c scalars, 4
#define BOFF  (COFF + 4)              // folded biases, 2*72
#define PREPN (BOFF + 144)

__device__ float  g_prep[PREPN];
__device__ __half g_h16[2*NN*HPAD];   // [A rows | B rows] fp16 padded
__device__ float  g_f36[2*NN*APAD];   // padded fp32 features (for update)
__device__ float  g_sc[8*NN];         // SA(t)=t*NN (dest-side), SB(t)=(4+t)*NN (src-side)
__device__ float  g_agg0[NN*APAD];
__device__ float  g_agg1[NN*APAD];

// ---- packed fp32x2 helpers (Blackwell f32x2 pipe) ----
__device__ __forceinline__ ull pk(float lo, float hi) {
    ull r; asm("mov.b64 %0,{%1,%2};" : "=l"(r) : "f"(lo), "f"(hi)); return r;
}
__device__ __forceinline__ void upk(ull v, float& lo, float& hi) {
    asm("mov.b64 {%0,%1},%2;" : "=f"(lo), "=f"(hi) : "l"(v));
}
__device__ __forceinline__ void ffma2(ull& d, ull a, ull b) {
    asm("fma.rn.f32x2 %0,%1,%2,%0;" : "+l"(d) : "l"(a), "l"(b));
}

// ============ prep: fold W into W1 (Wc = W @ W1_mid), v = W@att2, c = b.att2, bias fold ====
__global__ void prep_kernel(const float* __restrict__ W0, const float* __restrict__ A0, const float* __restrict__ B0,
                            const float* __restrict__ Wt1, const float* __restrict__ A1, const float* __restrict__ B1,
                            const float* __restrict__ Wt2, const float* __restrict__ A2, const float* __restrict__ B2,
                            const float* __restrict__ Wt3, const float* __restrict__ A3, const float* __restrict__ B3,
                            const float* __restrict__ W1, const float* __restrict__ b1) {
    const float* Wt[4] = {W0, Wt1, Wt2, Wt3};
    const float* At[4] = {A0, A1, A2, A3};
    const float* Bt[4] = {B0, B1, B2, B3};
    for (int idx = blockIdx.x * blockDim.x + threadIdx.x; idx < PREPN; idx += gridDim.x * blockDim.x) {
        float val = 0.f;
        if (idx < VOFF) {
            int t = idx / WCSZ, r = idx % WCSZ, k = r / 72, o = r % 72;
            if (k < 35 && o < 70) {
                int mid = (t & 1) ? 70 : 35;          // pos tags -> W1 rows 35:70, neg -> 70:105
                const float* w = Wt[t] + k * EMB;
                for (int e = 0; e < EMB; e++) val += w[e] * W1[(mid + e) * 70 + o];
            }
        } else if (idx < COFF) {
            int j = idx - VOFF; int t = j / EMB, k = j % EMB;
            const float* w = Wt[t] + k * EMB; const float* a = At[t] + EMB;
            for (int e = 0; e < EMB; e++) val += w[e] * a[e];
        } else if (idx < BOFF) {
            int t = idx - COFF;
            const float* a = At[t] + EMB; const float* bb = Bt[t];
            for (int e = 0; e < EMB; e++) val += bb[e] * a[e];
        } else {
            int j = idx - BOFF; int s = j / 72, o = j % 72;
            if (o < 70) {
                val = b1[o];
                const float* bp = Bt[s * 2]; const float* bn = Bt[s * 2 + 1];
                for (int e = 0; e < EMB; e++)
                    val += bp[e] * W1[(35 + e) * 70 + o] + bn[e] * W1[(70 + e) * 70 + o];
            }
        }
        g_prep[idx] = val;
    }
}

// ============ encode: fp16 rows + padded fp32 rows + 4 attention scores per node ============
__global__ void encode_kernel(const float* __restrict__ fa, const float* __restrict__ fb,
                              const float* __restrict__ att0, const float* __restrict__ att1,
                              const float* __restrict__ att2, const float* __restrict__ att3) {
    int i = blockIdx.x * blockDim.x + threadIdx.x;
    if (i >= 2 * NN) return;
    int side = (i >= NN) ? 1 : 0;
    int node = side ? i - NN : i;
    const float* src = (side ? fb : fa) + (size_t)node * EMB;

    float x[EMB];
#pragma unroll
    for (int k = 0; k < EMB; k++) x[k] = src[k];

    // fp16 padded row (zeros beyond dim 34)
    unsigned u[32];
#pragma unroll
    for (int p = 0; p < 32; p++) {
        float lo = (2 * p     < EMB) ? x[2 * p]     : 0.f;
        float hi = (2 * p + 1 < EMB) ? x[2 * p + 1] : 0.f;
        __half2 hh = __floats2half2_rn(lo, hi);
        u[p] = *reinterpret_cast<unsigned*>(&hh);
    }
    uint4* orow = reinterpret_cast<uint4*>(g_h16 + (size_t)i * HPAD);
#pragma unroll
    for (int q = 0; q < 8; q++) orow[q] = make_uint4(u[4 * q], u[4 * q + 1], u[4 * q + 2], u[4 * q + 3]);

    // fp32 padded row
    float* frow = g_f36 + (size_t)i * APAD;
#pragma unroll
    for (int k = 0; k < EMB; k++) frow[k] = x[k];
    frow[35] = 0.f;

    // scores
    const float* v0 = g_prep + VOFF;
    const float* v1 = g_prep + VOFF + EMB;
    const float* v2 = g_prep + VOFF + 2 * EMB;
    const float* v3 = g_prep + VOFF + 3 * EMB;
    float s0 = 0.f, s1 = 0.f, s2, s3;
    if (!side) {
        s2 = g_prep[COFF + 2]; s3 = g_prep[COFF + 3];
#pragma unroll
        for (int k = 0; k < EMB; k++) {
            s0 += x[k] * att0[k]; s1 += x[k] * att1[k];
            s2 += x[k] * v2[k];   s3 += x[k] * v3[k];
        }
        g_sc[0 * NN + node] = s0;        // sa_abp (A dest)
        g_sc[1 * NN + node] = s1;        // sa_abn
        g_sc[6 * NN + node] = s2;        // sb_bap (A as source)
        g_sc[7 * NN + node] = s3;        // sb_ban
    } else {
        s2 = g_prep[COFF + 0]; s3 = g_prep[COFF + 1];
#pragma unroll
        for (int k = 0; k < EMB; k++) {
            s0 += x[k] * att2[k]; s1 += x[k] * att3[k];
            s2 += x[k] * v0[k];   s3 += x[k] * v1[k];
        }
        g_sc[2 * NN + node] = s0;        // sa_bap (B dest)
        g_sc[3 * NN + node] = s1;        // sa_ban
        g_sc[4 * NN + node] = s2;        // sb_abp (B as source)
        g_sc[5 * NN + node] = s3;        // sb_abn
    }
}

// ============ fused pos+neg aggregation: warp per node, fp16 1-line gathers ============
__global__ void aggregate2_kernel(const float* __restrict__ sa0, const float* __restrict__ sa1,
                                  const float* __restrict__ sb0, const float* __restrict__ sb1,
                                  const int* __restrict__ dst0, const int* __restrict__ dst1,
                                  const __half* __restrict__ src,
                                  float* __restrict__ out0, float* __restrict__ out1) {
    int warp = (blockIdx.x * blockDim.x + threadIdx.x) >> 5;
    int lane = threadIdx.x & 31;
    if (warp >= NN) return;

    float a0s = sa0[warp], a1s = sa1[warp];
    int d0 = dst0[warp * DEG + lane];
    int d1 = dst1[warp * DEG + lane];
    float s0 = a0s + sb0[d0], s1 = a1s + sb1[d1];
    float e0 = s0 > 0.f ? s0 : 0.1f * expm1f(s0);
    float e1 = s1 > 0.f ? s1 : 0.1f * expm1f(s1);
    float w0 = __expf(e0), w1 = __expf(e1);

    float den0 = w0, den1 = w1;
#pragma unroll
    for (int o = 16; o; o >>= 1) {
        den0 += __shfl_xor_sync(0xffffffffu, den0, o);
        den1 += __shfl_xor_sync(0xffffffffu, den1, o);
    }

    float4 A0 = {0.f, 0.f, 0.f, 0.f}, A1 = {0.f, 0.f, 0.f, 0.f};
    const uint2* base = reinterpret_cast<const uint2*>(src);   // 16 uint2 per 64-half row
#pragma unroll
    for (int j = 0; j < DEG; j++) {
        float wj0 = __shfl_sync(0xffffffffu, w0, j);
        int   dj0 = __shfl_sync(0xffffffffu, d0, j);
        float wj1 = __shfl_sync(0xffffffffu, w1, j);
        int   dj1 = __shfl_sync(0xffffffffu, d1, j);
        if (lane < 9) {
            uint2 r0 = base[(size_t)dj0 * 16 + lane];
            uint2 r1 = base[(size_t)dj1 * 16 + lane];
            __half2 p00 = *reinterpret_cast<__half2*>(&r0.x);
            __half2 p01 = *reinterpret_cast<__half2*>(&r0.y);
            __half2 p10 = *reinterpret_cast<__half2*>(&r1.x);
            __half2 p11 = *reinterpret_cast<__half2*>(&r1.y);
            float2 f00 = __half22float2(p00), f01 = __half22float2(p01);
            float2 f10 = __half22float2(p10), f11 = __half22float2(p11);
            A0.x = fmaf(wj0, f00.x, A0.x); A0.y = fmaf(wj0, f00.y, A0.y);
            A0.z = fmaf(wj0, f01.x, A0.z); A0.w = fmaf(wj0, f01.y, A0.w);
            A1.x = fmaf(wj1, f10.x, A1.x); A1.y = fmaf(wj1, f10.y, A1.y);
            A1.z = fmaf(wj1, f11.x, A1.z); A1.w = fmaf(wj1, f11.y, A1.w);
        }
    }
    if (lane < 9) {
        float i0 = 1.f / den0, i1 = 1.f / den1;
        reinterpret_cast<float4*>(out0 + (size_t)warp * APAD)[lane] =
            make_float4(A0.x * i0, A0.y * i0, A0.z * i0, A0.w * i0);
        reinterpret_cast<float4*>(out1 + (size_t)warp * APAD)[lane] =
            make_float4(A1.x * i1, A1.y * i1, A1.z * i1, A1.w * i1);
    }
}

// ============ update MLP with folded weights, packed f32x2 FMA ============
__global__ void __launch_bounds__(128) update_kernel(
        const float* __restrict__ fsrc,                         // padded [NN][36]
        const float* __restrict__ aggp, const float* __restrict__ aggn,
        const float* __restrict__ W1,                           // gmem [105][70] (rows 0:35 used)
        const float* __restrict__ Wcp, const float* __restrict__ Wcn,  // [36][72] padded
        const float* __restrict__ bfold,                        // [72]
        const float* __restrict__ alpha,
        const float* __restrict__ W2, const float* __restrict__ b2,
        float* __restrict__ out) {
    __shared__ __align__(16) float sW[3][36 * 72];
    __shared__ __align__(16) float sW2[70 * 36];
    __shared__ __align__(16) float sbf[72];
    __shared__ __align__(16) float sb2[36];
    int tid = threadIdx.x;
    for (int i = tid; i < 36 * 72; i += blockDim.x) {
        int k = i / 72, o = i % 72;
        sW[0][i] = (k < 35 && o < 70) ? W1[k * 70 + o] : 0.f;
        sW[1][i] = Wcp[i];
        sW[2][i] = Wcn[i];
    }
    for (int i = tid; i < 70 * 36; i += blockDim.x) {
        int k = i / 36, o = i % 36;
        sW2[i] = (o < 35) ? W2[k * 35 + o] : 0.f;
    }
    if (tid < 72) sbf[tid] = bfold[tid];
    if (tid < 36) sb2[tid] = (tid < 35) ? b2[tid] : 0.f;
    __syncthreads();

    int row = blockIdx.x * blockDim.x + tid;
    if (row >= NN) return;
    float al = alpha[0];

    ull h2[35];
#pragma unroll
    for (int p = 0; p < 35; p++) h2[p] = pk(sbf[2 * p], sbf[2 * p + 1]);

    const float* srcs[3] = { fsrc + (size_t)row * APAD,
                             aggp + (size_t)row * APAD,
                             aggn + (size_t)row * APAD };
    for (int s = 0; s < 3; s++) {
        const float4* xv4 = reinterpret_cast<const float4*>(srcs[s]);
        const float* Wb = sW[s];
        for (int q = 0; q < 9; q++) {
            float4 xv = xv4[q];
            const float* wq = Wb + q * 4 * 72;
            {
                ull x2 = pk(xv.x, xv.x); const ull* wr = (const ull*)(wq);
#pragma unroll
                for (int p = 0; p < 35; p++) ffma2(h2[p], x2, wr[p]);
            }
            {
                ull x2 = pk(xv.y, xv.y); const ull* wr = (const ull*)(wq + 72);
#pragma unroll
                for (int p = 0; p < 35; p++) ffma2(h2[p], x2, wr[p]);
            }
            {
                ull x2 = pk(xv.z, xv.z); const ull* wr = (const ull*)(wq + 144);
#pragma unroll
                for (int p = 0; p < 35; p++) ffma2(h2[p], x2, wr[p]);
            }
            {
                ull x2 = pk(xv.w, xv.w); const ull* wr = (const ull*)(wq + 216);
#pragma unroll
                for (int p = 0; p < 35; p++) ffma2(h2[p], x2, wr[p]);
            }
        }
    }

    float h[70];
#pragma unroll
    for (int p = 0; p < 35; p++) {
        float lo, hi; upk(h2[p], lo, hi);
        h[2 * p]     = lo > 0.f ? lo : al * lo;
        h[2 * p + 1] = hi > 0.f ? hi : al * hi;
    }

    ull o2[18];
#pragma unroll
    for (int p = 0; p < 18; p++) o2[p] = pk(sb2[2 * p], sb2[2 * p + 1]);
#pragma unroll
    for (int k = 0; k < 70; k++) {
        ull x2 = pk(h[k], h[k]);
        const ull* wr = (const ull*)(sW2 + k * 36);
#pragma unroll
        for (int p = 0; p < 18; p++) ffma2(o2[p], x2, wr[p]);
    }

    float* op = out + (size_t)row * EMB;
#pragma unroll
    for (int p = 0; p < 17; p++) {
        float lo, hi; upk(o2[p], lo, hi);
        op[2 * p] = lo; op[2 * p + 1] = hi;
    }
    { float lo, hi; upk(o2[17], lo, hi); op[34] = lo; (void)hi; }
}

// ============ launch ============
extern "C" void kernel_launch(void* const* d_in, const int* in_sizes, int n_in,
                              void* d_out, int out_size) {
    const float* fa    = (const float*)d_in[0];
    const float* fb    = (const float*)d_in[1];
    const int*   dab_p = (const int*)  d_in[2];
    const int*   dab_n = (const int*)  d_in[3];
    const int*   dba_p = (const int*)  d_in[4];
    const int*   dba_n = (const int*)  d_in[5];
    const float* W_abp = (const float*)d_in[6];
    const float* b_abp = (const float*)d_in[7];
    const float* a_abp = (const float*)d_in[8];
    const float* W_abn = (const float*)d_in[9];
    const float* b_abn = (const float*)d_in[10];
    const float* a_abn = (const float*)d_in[11];
    const float* W_bap = (const float*)d_in[12];
    const float* b_bap = (const float*)d_in[13];
    const float* a_bap = (const float*)d_in[14];
    const float* W_ban = (const float*)d_in[15];
    const float* b_ban = (const float*)d_in[16];
    const float* a_ban = (const float*)d_in[17];
    const float* W1    = (const float*)d_in[18];
    const float* b1    = (const float*)d_in[19];
    const float* alpha = (const float*)d_in[20];
    const float* W2    = (const float*)d_in[21];
    const float* b2    = (const float*)d_in[22];
    float* out = (float*)d_out;

    float *prep, *f36, *sc, *agg0, *agg1;
    __half* h16;
    cudaGetSymbolAddress((void**)&prep, g_prep);
    cudaGetSymbolAddress((void**)&h16,  g_h16);
    cudaGetSymbolAddress((void**)&f36,  g_f36);
    cudaGetSymbolAddress((void**)&sc,   g_sc);
    cudaGetSymbolAddress((void**)&agg0, g_agg0);
    cudaGetSymbolAddress((void**)&agg1, g_agg1);

    prep_kernel<<<48, 256>>>(W_abp, a_abp, b_abp, W_abn, a_abn, b_abn,
                             W_bap, a_bap, b_bap, W_ban, a_ban, b_ban, W1, b1);
    encode_kernel<<<(2 * NN + 255) / 256, 256>>>(fa, fb, a_abp, a_abn, a_bap, a_ban);

    // side A: dest=A, source=B rows
    aggregate2_kernel<<<(NN * 32 + 255) / 256, 256>>>(
        sc + 0 * NN, sc + 1 * NN, sc + 4 * NN, sc + 5 * NN,
        dab_p, dab_n, h16 + (size_t)NN * HPAD, agg0, agg1);
    update_kernel<<<(NN + 127) / 128, 128>>>(
        f36, agg0, agg1, W1,
        prep + 0 * WCSZ, prep + 1 * WCSZ, prep + BOFF,
        alpha, W2, b2, out);

    // side B: dest=B, source=A rows
    aggregate2_kernel<<<(NN * 32 + 255) / 256, 256>>>(
        sc + 2 * NN, sc + 3 * NN, sc + 6 * NN, sc + 7 * NN,
        dba_p, dba_n, h16, agg0, agg1);
    update_kernel<<<(NN + 127) / 128, 128>>>(
        f36 + (size_t)NN * APAD, agg0, agg1, W1,
        prep + 2 * WCSZ, prep + 3 * WCSZ, prep + BOFF + 72,
        alpha, W2, b2, out + (size_t)NN * EMB);

    (void)in_sizes; (void)n_in; (void)out_size;
}